// round 14
// baseline (speedup 1.0000x reference)
#include <cuda_runtime.h>
#include <cstdint>

#define S_LEN 1024
#define B_SZ  128
#define H_SZ  512
#define C_OUT 128

typedef unsigned long long ull;

// ---------------- f32x2 packed-FMA helpers (bit-identical per lane) ----------------
__device__ __forceinline__ ull ffma2(ull a, ull b, ull c) {
    ull d;
    asm("fma.rn.f32x2 %0, %1, %2, %3;" : "=l"(d) : "l"(a), "l"(b), "l"(c));
    return d;
}
__device__ __forceinline__ ull dup2(float v) {
    ull d;
    asm("mov.b64 %0, {%1, %1};" : "=l"(d) : "f"(v));
    return d;
}
__device__ __forceinline__ float2 unpack2(ull p) {
    float2 r;
    asm("mov.b64 {%0, %1}, %2;" : "=f"(r.x), "=f"(r.y) : "l"(p));
    return r;
}

// ---------------- device scratch ----------------
__device__ float g_buf[16 * 512 * 8];                // final mem: [cluster][h][b]
__device__ int   g_cnt;

__global__ void init_kernel() { g_cnt = 0; }

// ---------------- fused persistent kernel ----------------
__device__ __forceinline__ unsigned smem_u32_addr(const void* p) {
    unsigned a;
    asm("{ .reg .u64 t; cvta.to.shared.u64 t, %1; cvt.u32.u64 %0, t; }"
        : "=r"(a) : "l"(p));
    return a;
}

#define CLUSTER_BARRIER() \
    asm volatile("barrier.cluster.arrive.aligned;\n\tbarrier.cluster.wait.aligned;" ::: "memory")

// smem layout (float offsets)
#define WT_OFF    0                  // [64][256]  T weights (x part of W_tau), [c][k]
#define WG_OFF    16384              // [64][256]  G weights (W_in), [c][k]
#define MEMB_OFFF 32768              // [2][512][8]
#define PART_OFFF 40960              // [16][512]
#define XT_OFF    49152              // [4][256][2]  x pairs: [bp][k]{b even, b odd}
#define TSM_OFF   51200              // [512]  T vals: [c*8 + b]
#define GSM_OFF   51712              // [512]
// byte offsets
#define MEMB_BYTE 131072             // 32768 floats * 4
#define MBAR_OFFB 208896             // 52224 floats * 4; [2][8] x u64
#define REC_SMEM  (MBAR_OFFB + 128)

__global__ void __cluster_dims__(8, 1, 1) __launch_bounds__(512, 1)
fused_kernel(const float* __restrict__ x, const float* __restrict__ Win,
             const float* __restrict__ bin, const float* __restrict__ Wtau,
             const float* __restrict__ btl, const float* __restrict__ bt)
{
    extern __shared__ float sm[];
    float* wTs  = sm + WT_OFF;
    float* wGs  = sm + WG_OFF;
    float* memB = sm + MEMB_OFFF;
    float* part = sm + PART_OFFF;
    float* xT2  = sm + XT_OFF;
    float* Tsm  = sm + TSM_OFF;
    float* Gsm  = sm + GSM_OFF;

    const int tid  = threadIdx.x;
    const int lane = tid & 31;
    const int w    = tid >> 5;                 // 0..15
    const int r    = blockIdx.x & 7;           // cluster rank -> column slice
    const int cl   = blockIdx.x >> 3;          // cluster index -> 8 batch rows
    const int b0   = cl * 8;

    const int k0 = w * 32;                     // mem warp K-split (R12)

    // mem weights in registers (R12 verbatim)
    float wreg[64];
    {
        const float* wsrc = Wtau + (size_t)(256 + k0) * 512 + r * 64 + 2 * lane;
#pragma unroll
        for (int kk = 0; kk < 32; kk++) {
            const float2 wv = *(const float2*)(wsrc + (size_t)kk * 512);
            wreg[2 * kk]     = wv.x;
            wreg[2 * kk + 1] = wv.y;
        }
    }

    // T/G weights into smem, [c][k] layout
    for (int idx = tid; idx < 64 * 256; idx += 512) {
        const int k = idx >> 6, c = idx & 63;
        wTs[c * 256 + k] = Wtau[(size_t)k * 512 + r * 64 + c];
        wGs[c * 256 + k] = Win[(size_t)k * 512 + r * 64 + c];
    }
    // zero both mem buffers
    for (int idx = tid; idx < 2 * 512 * 8; idx += 512) memB[idx] = 0.f;

    const unsigned sbase = smem_u32_addr(sm);
    const unsigned mbar_base = sbase + MBAR_OFFB;
    if (tid < 16) {
        asm volatile("mbarrier.init.shared.b64 [%0], %1;"
                     :: "r"(mbar_base + tid * 8), "r"(1) : "memory");
    }
    unsigned pbase[8];
#pragma unroll
    for (int q = 0; q < 8; q++)
        asm("mapa.shared::cluster.u32 %0, %1, %2;" : "=r"(pbase[q]) : "r"(sbase), "r"(q));

    // elementwise role
    const int ce = tid & 63;
    const int bb = tid >> 6;
    const int gh = r * 64 + ce;
    const int src = w >> 1;
    const unsigned my_mbar_b0 = mbar_base + (unsigned)(src * 8);
    const unsigned my_mbar_b1 = mbar_base + (unsigned)(64 + src * 8);

    // T/G role (warps 0..7): u in 0..3; c = (u&1)*32 + lane; batch-pair group = (u>>1)*2
    const int u    = (w < 4) ? w : (w - 4);
    const int c_tg = (u & 1) * 32 + lane;
    const int bpA  = (u >> 1) * 2;             // pair indices bpA, bpA+1 -> batches 2*bpA .. 2*bpA+3
    float biasv = 0.f;
    if (w < 8) {
        const int ghc = r * 64 + c_tg;
        biasv = (w < 4) ? (btl[ghc] + bt[ghc]) : bin[ghc];
    }

    // x staging base: thread loads x[b0+bx][t][k4*4 .. +3]
    const int bx = tid >> 6, k4 = tid & 63;
    const float* xbase = x + ((size_t)(b0 + bx) * 1024) * 256 + k4 * 4;
    const int xbp = bx >> 1, xe = bx & 1;
    float* xdst = xT2 + ((size_t)(xbp * 256 + k4 * 4)) * 2 + xe;

    // stage x(0)
    {
        const float4 xr0 = *(const float4*)(xbase);
        xdst[0] = xr0.x; xdst[2] = xr0.y; xdst[4] = xr0.z; xdst[6] = xr0.w;
    }
    CLUSTER_BARRIER();   // weights/memB/xT2/mbar visible cluster-wide

    float cnt = 0.f;

    for (int t = 0; t < S_LEN; t++) {
        const int cb = t & 1, nb = cb ^ 1;

        // prefetch x(t+1)
        float4 xr = make_float4(0.f, 0.f, 0.f, 0.f);
        if (t < S_LEN - 1) xr = *(const float4*)(xbase + (size_t)(t + 1) * 256);

        // ---- T/G GEMM (warps 0..7): full 256-k ascending chains, bit-identical ----
        if (w < 8) {
            ull a0 = 0ull, a1 = 0ull;
            const float* wrow = ((w < 4) ? wTs : wGs) + (size_t)c_tg * 256;
            const float* xp0 = xT2 + (size_t)bpA * 512;
            const float* xp1 = xp0 + 512;
            for (int kq = 0; kq < 64; kq++) {
                const float4 wv = *(const float4*)(wrow + kq * 4);
                const ulonglong2 xa = *(const ulonglong2*)(xp0 + kq * 8);
                const ulonglong2 xb = *(const ulonglong2*)(xp0 + kq * 8 + 4);
                const ulonglong2 xc = *(const ulonglong2*)(xp1 + kq * 8);
                const ulonglong2 xd = *(const ulonglong2*)(xp1 + kq * 8 + 4);
                const ull w0 = dup2(wv.x), w1 = dup2(wv.y);
                const ull w2 = dup2(wv.z), w3 = dup2(wv.w);
                a0 = ffma2(xa.x, w0, a0);  a1 = ffma2(xc.x, w0, a1);
                a0 = ffma2(xa.y, w1, a0);  a1 = ffma2(xc.y, w1, a1);
                a0 = ffma2(xb.x, w2, a0);  a1 = ffma2(xd.x, w2, a1);
                a0 = ffma2(xb.y, w3, a0);  a1 = ffma2(xd.y, w3, a1);
            }
            const float2 f0 = unpack2(a0);   // batches 2*bpA, 2*bpA+1
            const float2 f1 = unpack2(a1);   // batches 2*bpA+2, 2*bpA+3
            float* dstTG = (w < 4) ? Tsm : Gsm;
            *(float2*)&dstTG[c_tg * 8 + 2 * bpA]     = make_float2(f0.x + biasv, f0.y + biasv);
            *(float2*)&dstTG[c_tg * 8 + 2 * bpA + 2] = make_float2(f1.x + biasv, f1.y + biasv);
        }

        // ---- per-warp wait: only my source slice of buffer cb must have landed ----
        if (t > 0) {
            const unsigned ph = (unsigned)(((t - 1) >> 1) & 1);
            const unsigned mb = cb ? my_mbar_b1 : my_mbar_b0;
            asm volatile(
                "{\n\t"
                ".reg .pred P;\n\t"
                "W_%=:\n\t"
                "mbarrier.try_wait.parity.acquire.cta.shared::cta.b64 P, [%0], %1, 0x989680;\n\t"
                "@P bra D_%=;\n\t"
                "bra W_%=;\n\t"
                "D_%=:\n\t"
                "}"
                :: "r"(mb), "r"(ph) : "memory");
        }

        // ---- mem GEMM (R12 verbatim) ----
        ull pa[4], pb[4];
#pragma unroll
        for (int j = 0; j < 4; j++) { pa[j] = 0ull; pb[j] = 0ull; }

        const float* mp = memB + cb * 4096 + k0 * 8;
#pragma unroll
        for (int kk = 0; kk < 32; kk++) {
            const ulonglong2 m01 = *(const ulonglong2*)(mp + kk * 8);
            const ulonglong2 m23 = *(const ulonglong2*)(mp + kk * 8 + 4);
            const ull w0d = dup2(wreg[2 * kk]);
            const ull w1d = dup2(wreg[2 * kk + 1]);
            pa[0] = ffma2(m01.x, w0d, pa[0]);
            pa[1] = ffma2(m01.y, w0d, pa[1]);
            pa[2] = ffma2(m23.x, w0d, pa[2]);
            pa[3] = ffma2(m23.y, w0d, pa[3]);
            pb[0] = ffma2(m01.x, w1d, pb[0]);
            pb[1] = ffma2(m01.y, w1d, pb[1]);
            pb[2] = ffma2(m23.x, w1d, pb[2]);
            pb[3] = ffma2(m23.y, w1d, pb[3]);
        }
#pragma unroll
        for (int j = 0; j < 4; j++) {
            const float2 fa = unpack2(pa[j]);
            const float2 fb = unpack2(pb[j]);
            *(float2*)&part[w * 512 + (2 * j)     * 64 + 2 * lane] = make_float2(fa.x, fb.x);
            *(float2*)&part[w * 512 + (2 * j + 1) * 64 + 2 * lane] = make_float2(fa.y, fb.y);
        }
        __syncthreads();

        // ---- reduce 16 partials + elementwise update ----
        float s = 0.f;
#pragma unroll
        for (int ww = 0; ww < 16; ww++)
            s += part[ww * 512 + bb * 64 + ce];
        const float Tv = Tsm[ce * 8 + bb];
        const float Gv = Gsm[ce * 8 + bb];
        const float l = Tv + s;
        float beta = 1.f / (1.f + expf(-l));
        beta = fminf(fmaxf(beta, 0.01f), 0.99f);
        const float mo = memB[cb * 4096 + gh * 8 + bb];
        float mn = fmaf(beta, mo, Gv);
        const float sp = ((mn - 1.0f) > 0.0f) ? 1.f : 0.f;
        mn -= sp;
        cnt += sp;

        if (t < S_LEN - 1) {
            memB[nb * 4096 + gh * 8 + bb] = mn;
            // stage x(t+1) (readers of xT2(t) finished before sync1)
            xdst[0] = xr.x; xdst[2] = xr.y; xdst[4] = xr.z; xdst[6] = xr.w;
            __syncthreads();

            if (tid == 0) {
                asm volatile("fence.proxy.async;" ::: "memory");
#pragma unroll
                for (int q = 0; q < 8; q++) {
                    const unsigned mb = mbar_base + (unsigned)((nb * 8 + q) * 8);
                    if (q == r) {
                        asm volatile("mbarrier.arrive.shared.b64 _, [%0];"
                                     :: "r"(mb) : "memory");
                    } else {
                        asm volatile("mbarrier.arrive.expect_tx.shared.b64 _, [%0], %1;"
                                     :: "r"(mb), "r"(2048) : "memory");
                    }
                }
                const unsigned srcaddr = sbase + MEMB_BYTE + (unsigned)(nb * 16384 + r * 2048);
                const unsigned doff = MEMB_BYTE + (unsigned)(nb * 16384 + r * 2048);
                const unsigned moff = MBAR_OFFB + (unsigned)((nb * 8 + r) * 8);
#pragma unroll
                for (int i = 1; i < 8; i++) {
                    const int q = (r + i) & 7;
                    asm volatile(
                        "cp.async.bulk.shared::cluster.shared::cta.mbarrier::complete_tx::bytes"
                        " [%0], [%1], %2, [%3];"
                        :: "r"(pbase[q] + doff), "r"(srcaddr), "r"(2048), "r"(pbase[q] + moff)
                        : "memory");
                }
            }
        } else {
            asm volatile("st.global.cg.f32 [%0], %1;"
                         :: "l"(g_buf + (size_t)cl * 4096 + gh * 8 + bb), "f"(mn) : "memory");
        }
    }

    // spike-count reduction
    __syncthreads();
    part[tid] = cnt;
    __syncthreads();
    if (tid < 256) part[tid] += part[tid + 256];
    __syncthreads();
    if (tid < 128) part[tid] += part[tid + 128];
    __syncthreads();
    if (tid < 64) part[tid] += part[tid + 64];
    __syncthreads();
    if (tid < 32) {
        float v = part[tid] + part[tid + 32];
#pragma unroll
        for (int o = 16; o > 0; o >>= 1) v += __shfl_down_sync(0xffffffffu, v, o);
        if (tid == 0) atomicAdd(&g_cnt, (int)(v + 0.5f));
    }
    CLUSTER_BARRIER();   // no CTA exits while peers' copies may still target its smem
}

// ---------------- readout GEMM + sparsity ----------------
__global__ void readout_kernel(const float* __restrict__ Wro, const float* __restrict__ bro,
                               float* __restrict__ out, int out_size)
{
    __shared__ float mrow[512];
    const int row = blockIdx.x;
    const int tid = threadIdx.x;   // 128
    const float* src = g_buf + (size_t)(row >> 3) * 4096 + (row & 7);
    for (int i = tid; i < 512; i += 128) mrow[i] = src[i * 8];
    __syncthreads();
    float acc = bro[tid];
#pragma unroll 8
    for (int k = 0; k < 512; k++)
        acc = fmaf(mrow[k], Wro[(size_t)k * 128 + tid], acc);
    out[(size_t)row * 128 + tid] = acc;
    if (row == 0 && tid == 0 && out_size > B_SZ * C_OUT) {
        out[B_SZ * C_OUT] = 1.0f - (float)g_cnt / (float)((size_t)S_LEN * B_SZ * H_SZ);
    }
}

// ---------------- launch ----------------
extern "C" void kernel_launch(void* const* d_in, const int* in_sizes, int n_in,
                              void* d_out, int out_size)
{
    const float* x    = (const float*)d_in[0];
    const float* Win  = (const float*)d_in[1];
    const float* bin  = (const float*)d_in[2];
    const float* Wtau = (const float*)d_in[3];
    const float* btl  = (const float*)d_in[4];
    const float* bt   = (const float*)d_in[5];
    const float* Wro  = (const float*)d_in[6];
    const float* bro  = (const float*)d_in[7];

    init_kernel<<<1, 1>>>();

    cudaFuncSetAttribute(fused_kernel, cudaFuncAttributeMaxDynamicSharedMemorySize, REC_SMEM);
    fused_kernel<<<128, 512, REC_SMEM>>>(x, Win, bin, Wtau, btl, bt);

    readout_kernel<<<B_SZ, C_OUT>>>(Wro, bro, (float*)d_out, out_size);
}

// round 15
// speedup vs baseline: 2.3006x; 2.3006x over previous
#include <cuda_runtime.h>
#include <cstdint>

#define S_LEN 1024
#define B_SZ  128
#define H_SZ  512
#define C_OUT 128

typedef unsigned long long ull;

// ---------------- f32x2 packed-FMA helpers (bit-identical per lane) ----------------
__device__ __forceinline__ ull ffma2(ull a, ull b, ull c) {
    ull d;
    asm("fma.rn.f32x2 %0, %1, %2, %3;" : "=l"(d) : "l"(a), "l"(b), "l"(c));
    return d;
}
__device__ __forceinline__ ull dup2(float v) {
    ull d;
    asm("mov.b64 %0, {%1, %1};" : "=l"(d) : "f"(v));
    return d;
}
__device__ __forceinline__ float2 unpack2(ull p) {
    float2 r;
    asm("mov.b64 {%0, %1}, %2;" : "=f"(r.x), "=f"(r.y) : "l"(p));
    return r;
}

// ---------------- device scratch ----------------
__device__ float g_buf[16 * 512 * 8];                // final mem: [cluster][h][b]
__device__ int   g_cnt;

__global__ void init_kernel() { g_cnt = 0; }

// ---------------- fused persistent kernel ----------------
__device__ __forceinline__ unsigned smem_u32_addr(const void* p) {
    unsigned a;
    asm("{ .reg .u64 t; cvta.to.shared.u64 t, %1; cvt.u32.u64 %0, t; }"
        : "=r"(a) : "l"(p));
    return a;
}

#define CLUSTER_BARRIER() \
    asm volatile("barrier.cluster.arrive.aligned;\n\tbarrier.cluster.wait.aligned;" ::: "memory")

// padded weight row: 260 floats (1040 B) -> lane stride ≡ 4 words mod 32: conflict-free LDS.128
#define W_PAD     260
// smem layout (float offsets)
#define WT_OFF    0                        // [64][260]  T weights, [c][k]
#define WG_OFF    (64 * W_PAD)             // 16640
#define MEMB_OFFF (2 * 64 * W_PAD)         // 33280   [2][512][8]
#define PART_OFFF (MEMB_OFFF + 8192)       // 41472   [16][512]
#define XT_OFF    (PART_OFFF + 8192)       // 49664   [4][256][2]
#define TSM_OFF   (XT_OFF + 2048)          // 51712   [512]
#define GSM_OFF   (TSM_OFF + 512)          // 52224   [512]
// byte offsets
#define MEMB_BYTE (MEMB_OFFF * 4)          // 133120
#define MBAR_OFFB ((GSM_OFF + 512) * 4)    // 210944  [2][8] x u64
#define REC_SMEM  (MBAR_OFFB + 128)        // 211072 bytes

__global__ void __cluster_dims__(8, 1, 1) __launch_bounds__(512, 1)
fused_kernel(const float* __restrict__ x, const float* __restrict__ Win,
             const float* __restrict__ bin, const float* __restrict__ Wtau,
             const float* __restrict__ btl, const float* __restrict__ bt)
{
    extern __shared__ float sm[];
    float* wTs  = sm + WT_OFF;
    float* wGs  = sm + WG_OFF;
    float* memB = sm + MEMB_OFFF;
    float* part = sm + PART_OFFF;
    float* xT2  = sm + XT_OFF;
    float* Tsm  = sm + TSM_OFF;
    float* Gsm  = sm + GSM_OFF;

    const int tid  = threadIdx.x;
    const int lane = tid & 31;
    const int w    = tid >> 5;                 // 0..15
    const int r    = blockIdx.x & 7;           // cluster rank -> column slice
    const int cl   = blockIdx.x >> 3;          // cluster index -> 8 batch rows
    const int b0   = cl * 8;

    const int k0 = w * 32;                     // mem warp K-split (R12)

    // mem weights in registers (R12 verbatim)
    float wreg[64];
    {
        const float* wsrc = Wtau + (size_t)(256 + k0) * 512 + r * 64 + 2 * lane;
#pragma unroll
        for (int kk = 0; kk < 32; kk++) {
            const float2 wv = *(const float2*)(wsrc + (size_t)kk * 512);
            wreg[2 * kk]     = wv.x;
            wreg[2 * kk + 1] = wv.y;
        }
    }

    // T/G weights into smem, [c][k] layout with padded rows
    for (int idx = tid; idx < 64 * 256; idx += 512) {
        const int k = idx >> 6, c = idx & 63;
        wTs[c * W_PAD + k] = Wtau[(size_t)k * 512 + r * 64 + c];
        wGs[c * W_PAD + k] = Win[(size_t)k * 512 + r * 64 + c];
    }
    // zero both mem buffers
    for (int idx = tid; idx < 2 * 512 * 8; idx += 512) memB[idx] = 0.f;

    const unsigned sbase = smem_u32_addr(sm);
    const unsigned mbar_base = sbase + MBAR_OFFB;
    if (tid < 16) {
        asm volatile("mbarrier.init.shared.b64 [%0], %1;"
                     :: "r"(mbar_base + tid * 8), "r"(1) : "memory");
    }
    unsigned pbase[8];
#pragma unroll
    for (int q = 0; q < 8; q++)
        asm("mapa.shared::cluster.u32 %0, %1, %2;" : "=r"(pbase[q]) : "r"(sbase), "r"(q));

    // elementwise role
    const int ce = tid & 63;
    const int bb = tid >> 6;
    const int gh = r * 64 + ce;
    const int src = w >> 1;
    const unsigned my_mbar_b0 = mbar_base + (unsigned)(src * 8);
    const unsigned my_mbar_b1 = mbar_base + (unsigned)(64 + src * 8);

    // T/G role (warps 0..7): u in 0..3; c = (u&1)*32 + lane; batch-pair group = (u>>1)*2
    const int u    = (w < 4) ? w : (w - 4);
    const int c_tg = (u & 1) * 32 + lane;
    const int bpA  = (u >> 1) * 2;             // pairs bpA, bpA+1 -> batches 2*bpA .. 2*bpA+3
    float biasv = 0.f;
    if (w < 8) {
        const int ghc = r * 64 + c_tg;
        biasv = (w < 4) ? (btl[ghc] + bt[ghc]) : bin[ghc];
    }

    // x staging base: thread loads x[b0+bx][t][k4*4 .. +3]
    const int bx = tid >> 6, k4 = tid & 63;
    const float* xbase = x + ((size_t)(b0 + bx) * 1024) * 256 + k4 * 4;
    const int xbp = bx >> 1, xe = bx & 1;
    float* xdst = xT2 + ((size_t)(xbp * 256 + k4 * 4)) * 2 + xe;

    // stage x(0)
    {
        const float4 xr0 = *(const float4*)(xbase);
        xdst[0] = xr0.x; xdst[2] = xr0.y; xdst[4] = xr0.z; xdst[6] = xr0.w;
    }
    CLUSTER_BARRIER();   // weights/memB/xT2/mbar visible cluster-wide

    float cnt = 0.f;

    for (int t = 0; t < S_LEN; t++) {
        const int cb = t & 1, nb = cb ^ 1;

        // prefetch x(t+1)
        float4 xr = make_float4(0.f, 0.f, 0.f, 0.f);
        if (t < S_LEN - 1) xr = *(const float4*)(xbase + (size_t)(t + 1) * 256);

        // ---- T/G GEMM (warps 0..7): full 256-k ascending chains, bit-identical ----
        if (w < 8) {
            ull a0 = 0ull, a1 = 0ull;
            const float* wrow = ((w < 4) ? wTs : wGs) + (size_t)c_tg * W_PAD;
            const float* xp0 = xT2 + (size_t)bpA * 512;
            const float* xp1 = xp0 + 512;
#pragma unroll 4
            for (int kq = 0; kq < 64; kq++) {
                const float4 wv = *(const float4*)(wrow + kq * 4);
                const ulonglong2 xa = *(const ulonglong2*)(xp0 + kq * 8);
                const ulonglong2 xb = *(const ulonglong2*)(xp0 + kq * 8 + 4);
                const ulonglong2 xc = *(const ulonglong2*)(xp1 + kq * 8);
                const ulonglong2 xd = *(const ulonglong2*)(xp1 + kq * 8 + 4);
                const ull w0 = dup2(wv.x), w1 = dup2(wv.y);
                const ull w2 = dup2(wv.z), w3 = dup2(wv.w);
                a0 = ffma2(xa.x, w0, a0);  a1 = ffma2(xc.x, w0, a1);
                a0 = ffma2(xa.y, w1, a0);  a1 = ffma2(xc.y, w1, a1);
                a0 = ffma2(xb.x, w2, a0);  a1 = ffma2(xd.x, w2, a1);
                a0 = ffma2(xb.y, w3, a0);  a1 = ffma2(xd.y, w3, a1);
            }
            const float2 f0 = unpack2(a0);   // batches 2*bpA, 2*bpA+1
            const float2 f1 = unpack2(a1);   // batches 2*bpA+2, 2*bpA+3
            float* dstTG = (w < 4) ? Tsm : Gsm;
            *(float2*)&dstTG[c_tg * 8 + 2 * bpA]     = make_float2(f0.x + biasv, f0.y + biasv);
            *(float2*)&dstTG[c_tg * 8 + 2 * bpA + 2] = make_float2(f1.x + biasv, f1.y + biasv);
        }

        // ---- per-warp wait: only my source slice of buffer cb must have landed ----
        if (t > 0) {
            const unsigned ph = (unsigned)(((t - 1) >> 1) & 1);
            const unsigned mb = cb ? my_mbar_b1 : my_mbar_b0;
            asm volatile(
                "{\n\t"
                ".reg .pred P;\n\t"
                "W_%=:\n\t"
                "mbarrier.try_wait.parity.acquire.cta.shared::cta.b64 P, [%0], %1, 0x989680;\n\t"
                "@P bra D_%=;\n\t"
                "bra W_%=;\n\t"
                "D_%=:\n\t"
                "}"
                :: "r"(mb), "r"(ph) : "memory");
        }

        // ---- mem GEMM (R12 verbatim) ----
        ull pa[4], pb[4];
#pragma unroll
        for (int j = 0; j < 4; j++) { pa[j] = 0ull; pb[j] = 0ull; }

        const float* mp = memB + cb * 4096 + k0 * 8;
#pragma unroll
        for (int kk = 0; kk < 32; kk++) {
            const ulonglong2 m01 = *(const ulonglong2*)(mp + kk * 8);
            const ulonglong2 m23 = *(const ulonglong2*)(mp + kk * 8 + 4);
            const ull w0d = dup2(wreg[2 * kk]);
            const ull w1d = dup2(wreg[2 * kk + 1]);
            pa[0] = ffma2(m01.x, w0d, pa[0]);
            pa[1] = ffma2(m01.y, w0d, pa[1]);
            pa[2] = ffma2(m23.x, w0d, pa[2]);
            pa[3] = ffma2(m23.y, w0d, pa[3]);
            pb[0] = ffma2(m01.x, w1d, pb[0]);
            pb[1] = ffma2(m01.y, w1d, pb[1]);
            pb[2] = ffma2(m23.x, w1d, pb[2]);
            pb[3] = ffma2(m23.y, w1d, pb[3]);
        }
#pragma unroll
        for (int j = 0; j < 4; j++) {
            const float2 fa = unpack2(pa[j]);
            const float2 fb = unpack2(pb[j]);
            *(float2*)&part[w * 512 + (2 * j)     * 64 + 2 * lane] = make_float2(fa.x, fb.x);
            *(float2*)&part[w * 512 + (2 * j + 1) * 64 + 2 * lane] = make_float2(fa.y, fb.y);
        }
        __syncthreads();

        // ---- reduce 16 partials + elementwise update ----
        float s = 0.f;
#pragma unroll
        for (int ww = 0; ww < 16; ww++)
            s += part[ww * 512 + bb * 64 + ce];
        const float Tv = Tsm[ce * 8 + bb];
        const float Gv = Gsm[ce * 8 + bb];
        const float l = Tv + s;
        float beta = 1.f / (1.f + expf(-l));
        beta = fminf(fmaxf(beta, 0.01f), 0.99f);
        const float mo = memB[cb * 4096 + gh * 8 + bb];
        float mn = fmaf(beta, mo, Gv);
        const float sp = ((mn - 1.0f) > 0.0f) ? 1.f : 0.f;
        mn -= sp;
        cnt += sp;

        if (t < S_LEN - 1) {
            memB[nb * 4096 + gh * 8 + bb] = mn;
            // stage x(t+1) (readers of xT2(t) finished before sync1)
            xdst[0] = xr.x; xdst[2] = xr.y; xdst[4] = xr.z; xdst[6] = xr.w;
            __syncthreads();

            if (tid == 0) {
                asm volatile("fence.proxy.async;" ::: "memory");
#pragma unroll
                for (int q = 0; q < 8; q++) {
                    const unsigned mb = mbar_base + (unsigned)((nb * 8 + q) * 8);
                    if (q == r) {
                        asm volatile("mbarrier.arrive.shared.b64 _, [%0];"
                                     :: "r"(mb) : "memory");
                    } else {
                        asm volatile("mbarrier.arrive.expect_tx.shared.b64 _, [%0], %1;"
                                     :: "r"(mb), "r"(2048) : "memory");
                    }
                }
                const unsigned srcaddr = sbase + MEMB_BYTE + (unsigned)(nb * 16384 + r * 2048);
                const unsigned doff = MEMB_BYTE + (unsigned)(nb * 16384 + r * 2048);
                const unsigned moff = MBAR_OFFB + (unsigned)((nb * 8 + r) * 8);
#pragma unroll
                for (int i = 1; i < 8; i++) {
                    const int q = (r + i) & 7;
                    asm volatile(
                        "cp.async.bulk.shared::cluster.shared::cta.mbarrier::complete_tx::bytes"
                        " [%0], [%1], %2, [%3];"
                        :: "r"(pbase[q] + doff), "r"(srcaddr), "r"(2048), "r"(pbase[q] + moff)
                        : "memory");
                }
            }
        } else {
            asm volatile("st.global.cg.f32 [%0], %1;"
                         :: "l"(g_buf + (size_t)cl * 4096 + gh * 8 + bb), "f"(mn) : "memory");
        }
    }

    // spike-count reduction
    __syncthreads();
    part[tid] = cnt;
    __syncthreads();
    if (tid < 256) part[tid] += part[tid + 256];
    __syncthreads();
    if (tid < 128) part[tid] += part[tid + 128];
    __syncthreads();
    if (tid < 64) part[tid] += part[tid + 64];
    __syncthreads();
    if (tid < 32) {
        float v = part[tid] + part[tid + 32];
#pragma unroll
        for (int o = 16; o > 0; o >>= 1) v += __shfl_down_sync(0xffffffffu, v, o);
        if (tid == 0) atomicAdd(&g_cnt, (int)(v + 0.5f));
    }
    CLUSTER_BARRIER();   // no CTA exits while peers' copies may still target its smem
}

// ---------------- readout GEMM + sparsity ----------------
__global__ void readout_kernel(const float* __restrict__ Wro, const float* __restrict__ bro,
                               float* __restrict__ out, int out_size)
{
    __shared__ float mrow[512];
    const int row = blockIdx.x;
    const int tid = threadIdx.x;   // 128
    const float* src = g_buf + (size_t)(row >> 3) * 4096 + (row & 7);
    for (int i = tid; i < 512; i += 128) mrow[i] = src[i * 8];
    __syncthreads();
    float acc = bro[tid];
#pragma unroll 8
    for (int k = 0; k < 512; k++)
        acc = fmaf(mrow[k], Wro[(size_t)k * 128 + tid], acc);
    out[(size_t)row * 128 + tid] = acc;
    if (row == 0 && tid == 0 && out_size > B_SZ * C_OUT) {
        out[B_SZ * C_OUT] = 1.0f - (float)g_cnt / (float)((size_t)S_LEN * B_SZ * H_SZ);
    }
}

// ---------------- launch ----------------
extern "C" void kernel_launch(void* const* d_in, const int* in_sizes, int n_in,
                              void* d_out, int out_size)
{
    const float* x    = (const float*)d_in[0];
    const float* Win  = (const float*)d_in[1];
    const float* bin  = (const float*)d_in[2];
    const float* Wtau = (const float*)d_in[3];
    const float* btl  = (const float*)d_in[4];
    const float* bt   = (const float*)d_in[5];
    const float* Wro  = (const float*)d_in[6];
    const float* bro  = (const float*)d_in[7];

    init_kernel<<<1, 1>>>();

    cudaFuncSetAttribute(fused_kernel, cudaFuncAttributeMaxDynamicSharedMemorySize, REC_SMEM);
    fused_kernel<<<128, 512, REC_SMEM>>>(x, Win, bin, Wtau, btl, bt);

    readout_kernel<<<B_SZ, C_OUT>>>(Wro, bro, (float*)d_out, out_size);
}

// round 16
// speedup vs baseline: 2.3711x; 1.0307x over previous
#include <cuda_runtime.h>
#include <cstdint>

#define S_LEN 1024
#define B_SZ  128
#define H_SZ  512
#define C_OUT 128

typedef unsigned long long ull;

// ---------------- f32x2 packed-FMA helpers (bit-identical per lane) ----------------
__device__ __forceinline__ ull ffma2(ull a, ull b, ull c) {
    ull d;
    asm("fma.rn.f32x2 %0, %1, %2, %3;" : "=l"(d) : "l"(a), "l"(b), "l"(c));
    return d;
}
__device__ __forceinline__ ull dup2(float v) {
    ull d;
    asm("mov.b64 %0, {%1, %1};" : "=l"(d) : "f"(v));
    return d;
}
__device__ __forceinline__ float2 unpack2(ull p) {
    float2 r;
    asm("mov.b64 {%0, %1}, %2;" : "=f"(r.x), "=f"(r.y) : "l"(p));
    return r;
}

// ---------------- device scratch ----------------
__device__ float g_buf[16 * 512 * 8];                // final mem: [cluster][h][b]
__device__ int   g_cnt;

__global__ void init_kernel() { g_cnt = 0; }

// ---------------- fused persistent kernel ----------------
__device__ __forceinline__ unsigned smem_u32_addr(const void* p) {
    unsigned a;
    asm("{ .reg .u64 t; cvta.to.shared.u64 t, %1; cvt.u32.u64 %0, t; }"
        : "=r"(a) : "l"(p));
    return a;
}

#define CLUSTER_BARRIER() \
    asm volatile("barrier.cluster.arrive.aligned;\n\tbarrier.cluster.wait.aligned;" ::: "memory")

// padded weight row: 260 floats (1040 B) -> lane stride ≡ 4 words mod 32: conflict-free LDS.128
#define W_PAD     260
// smem layout (float offsets)
#define WT_OFF    0                        // [64][260]  T weights, [c][k]
#define WG_OFF    (64 * W_PAD)             // 16640
#define MEMB_OFFF (2 * 64 * W_PAD)         // 33280   [2][512][8]
#define PART_OFFF (MEMB_OFFF + 8192)       // 41472   [16][512]
#define XT_OFF    (PART_OFFF + 8192)       // 49664   [4][256][2]
#define TSM_OFF   (XT_OFF + 2048)          // 51712   [512]
#define GSM_OFF   (TSM_OFF + 512)          // 52224   [512]
// byte offsets
#define MEMB_BYTE (MEMB_OFFF * 4)          // 133120
#define MBAR_OFFB ((GSM_OFF + 512) * 4)    // 210944  [2][8] x u64
#define REC_SMEM  (MBAR_OFFB + 128)        // 211072 bytes

__global__ void __cluster_dims__(8, 1, 1) __launch_bounds__(512, 1)
fused_kernel(const float* __restrict__ x, const float* __restrict__ Win,
             const float* __restrict__ bin, const float* __restrict__ Wtau,
             const float* __restrict__ btl, const float* __restrict__ bt)
{
    extern __shared__ float sm[];
    float* wTs  = sm + WT_OFF;
    float* wGs  = sm + WG_OFF;
    float* memB = sm + MEMB_OFFF;
    float* part = sm + PART_OFFF;
    float* xT2  = sm + XT_OFF;
    float* Tsm  = sm + TSM_OFF;
    float* Gsm  = sm + GSM_OFF;

    const int tid  = threadIdx.x;
    const int lane = tid & 31;
    const int w    = tid >> 5;                 // 0..15
    const int r    = blockIdx.x & 7;           // cluster rank -> column slice
    const int cl   = blockIdx.x >> 3;          // cluster index -> 8 batch rows
    const int b0   = cl * 8;

    const int k0 = w * 32;                     // mem warp K-split (R12)

    // mem weights in registers (R12 verbatim)
    float wreg[64];
    {
        const float* wsrc = Wtau + (size_t)(256 + k0) * 512 + r * 64 + 2 * lane;
#pragma unroll
        for (int kk = 0; kk < 32; kk++) {
            const float2 wv = *(const float2*)(wsrc + (size_t)kk * 512);
            wreg[2 * kk]     = wv.x;
            wreg[2 * kk + 1] = wv.y;
        }
    }

    // T/G weights into smem, [c][k] layout with padded rows
    for (int idx = tid; idx < 64 * 256; idx += 512) {
        const int k = idx >> 6, c = idx & 63;
        wTs[c * W_PAD + k] = Wtau[(size_t)k * 512 + r * 64 + c];
        wGs[c * W_PAD + k] = Win[(size_t)k * 512 + r * 64 + c];
    }
    // zero both mem buffers
    for (int idx = tid; idx < 2 * 512 * 8; idx += 512) memB[idx] = 0.f;

    const unsigned sbase = smem_u32_addr(sm);
    const unsigned mbar_base = sbase + MBAR_OFFB;
    if (tid < 16) {
        asm volatile("mbarrier.init.shared.b64 [%0], %1;"
                     :: "r"(mbar_base + tid * 8), "r"(1) : "memory");
    }
    // NOTE: no per-thread pbase[] array — mapa recomputed by tid0 inside the loop
    // (keeps 8 registers free in every thread; critical for wreg residency).

    // elementwise role
    const int ce = tid & 63;
    const int bb = tid >> 6;
    const int gh = r * 64 + ce;
    const int src = w >> 1;
    const unsigned my_mbar_b0 = mbar_base + (unsigned)(src * 8);   // buffer1 = +64 bytes

    // T/G role (warps 0..7): u in 0..3; c = (u&1)*32 + lane; batch-pair group = (u>>1)*2
    const int u    = (w < 4) ? w : (w - 4);
    const int c_tg = (u & 1) * 32 + lane;
    const int bpA  = (u >> 1) * 2;             // pairs bpA, bpA+1 -> batches 2*bpA .. 2*bpA+3
    float biasv = 0.f;
    if (w < 8) {
        const int ghc = r * 64 + c_tg;
        biasv = (w < 4) ? (btl[ghc] + bt[ghc]) : bin[ghc];
    }

    // x staging base: thread loads x[b0+bx][t][k4*4 .. +3]
    const int bx = tid >> 6, k4 = tid & 63;
    const float* xbase = x + ((size_t)(b0 + bx) * 1024) * 256 + k4 * 4;
    float* xdst = xT2 + ((size_t)((bx >> 1) * 256 + k4 * 4)) * 2 + (bx & 1);

    // stage x(0)
    {
        const float4 xr0 = *(const float4*)(xbase);
        xdst[0] = xr0.x; xdst[2] = xr0.y; xdst[4] = xr0.z; xdst[6] = xr0.w;
    }
    CLUSTER_BARRIER();   // weights/memB/xT2/mbar visible cluster-wide

    float cnt = 0.f;

    for (int t = 0; t < S_LEN; t++) {
        const int cb = t & 1, nb = cb ^ 1;

        // prefetch x(t+1)
        float4 xr = make_float4(0.f, 0.f, 0.f, 0.f);
        if (t < S_LEN - 1) xr = *(const float4*)(xbase + (size_t)(t + 1) * 256);

        // ---- T/G GEMM (warps 0..7): full 256-k ascending chains, bit-identical ----
        if (w < 8) {
            ull a0 = 0ull, a1 = 0ull;
            const float* wrow = ((w < 4) ? wTs : wGs) + (size_t)c_tg * W_PAD;
            const float* xp0 = xT2 + (size_t)bpA * 512;
            const float* xp1 = xp0 + 512;
#pragma unroll 4
            for (int kq = 0; kq < 64; kq++) {
                const float4 wv = *(const float4*)(wrow + kq * 4);
                const ulonglong2 xa = *(const ulonglong2*)(xp0 + kq * 8);
                const ulonglong2 xb = *(const ulonglong2*)(xp0 + kq * 8 + 4);
                const ulonglong2 xc = *(const ulonglong2*)(xp1 + kq * 8);
                const ulonglong2 xd = *(const ulonglong2*)(xp1 + kq * 8 + 4);
                const ull w0 = dup2(wv.x), w1 = dup2(wv.y);
                const ull w2 = dup2(wv.z), w3 = dup2(wv.w);
                a0 = ffma2(xa.x, w0, a0);  a1 = ffma2(xc.x, w0, a1);
                a0 = ffma2(xa.y, w1, a0);  a1 = ffma2(xc.y, w1, a1);
                a0 = ffma2(xb.x, w2, a0);  a1 = ffma2(xd.x, w2, a1);
                a0 = ffma2(xb.y, w3, a0);  a1 = ffma2(xd.y, w3, a1);
            }
            const float2 f0 = unpack2(a0);   // batches 2*bpA, 2*bpA+1
            const float2 f1 = unpack2(a1);   // batches 2*bpA+2, 2*bpA+3
            float* dstTG = (w < 4) ? Tsm : Gsm;
            *(float2*)&dstTG[c_tg * 8 + 2 * bpA]     = make_float2(f0.x + biasv, f0.y + biasv);
            *(float2*)&dstTG[c_tg * 8 + 2 * bpA + 2] = make_float2(f1.x + biasv, f1.y + biasv);
        }

        // ---- per-warp wait: only my source slice of buffer cb must have landed ----
        if (t > 0) {
            const unsigned ph = (unsigned)(((t - 1) >> 1) & 1);
            const unsigned mb = my_mbar_b0 + (unsigned)(cb * 64);
            asm volatile(
                "{\n\t"
                ".reg .pred P;\n\t"
                "W_%=:\n\t"
                "mbarrier.try_wait.parity.acquire.cta.shared::cta.b64 P, [%0], %1, 0x989680;\n\t"
                "@P bra D_%=;\n\t"
                "bra W_%=;\n\t"
                "D_%=:\n\t"
                "}"
                :: "r"(mb), "r"(ph) : "memory");
        }

        // ---- mem GEMM (R12 verbatim) ----
        ull pa[4], pb[4];
#pragma unroll
        for (int j = 0; j < 4; j++) { pa[j] = 0ull; pb[j] = 0ull; }

        const float* mp = memB + cb * 4096 + k0 * 8;
#pragma unroll
        for (int kk = 0; kk < 32; kk++) {
            const ulonglong2 m01 = *(const ulonglong2*)(mp + kk * 8);
            const ulonglong2 m23 = *(const ulonglong2*)(mp + kk * 8 + 4);
            const ull w0d = dup2(wreg[2 * kk]);
            const ull w1d = dup2(wreg[2 * kk + 1]);
            pa[0] = ffma2(m01.x, w0d, pa[0]);
            pa[1] = ffma2(m01.y, w0d, pa[1]);
            pa[2] = ffma2(m23.x, w0d, pa[2]);
            pa[3] = ffma2(m23.y, w0d, pa[3]);
            pb[0] = ffma2(m01.x, w1d, pb[0]);
            pb[1] = ffma2(m01.y, w1d, pb[1]);
            pb[2] = ffma2(m23.x, w1d, pb[2]);
            pb[3] = ffma2(m23.y, w1d, pb[3]);
        }
#pragma unroll
        for (int j = 0; j < 4; j++) {
            const float2 fa = unpack2(pa[j]);
            const float2 fb = unpack2(pb[j]);
            *(float2*)&part[w * 512 + (2 * j)     * 64 + 2 * lane] = make_float2(fa.x, fb.x);
            *(float2*)&part[w * 512 + (2 * j + 1) * 64 + 2 * lane] = make_float2(fa.y, fb.y);
        }
        __syncthreads();

        // ---- reduce 16 partials + elementwise update ----
        float s = 0.f;
#pragma unroll
        for (int ww = 0; ww < 16; ww++)
            s += part[ww * 512 + bb * 64 + ce];
        const float Tv = Tsm[ce * 8 + bb];
        const float Gv = Gsm[ce * 8 + bb];
        const float l = Tv + s;
        float beta = 1.f / (1.f + expf(-l));
        beta = fminf(fmaxf(beta, 0.01f), 0.99f);
        const float mo = memB[cb * 4096 + gh * 8 + bb];
        float mn = fmaf(beta, mo, Gv);
        const float sp = ((mn - 1.0f) > 0.0f) ? 1.f : 0.f;
        mn -= sp;
        cnt += sp;

        if (t < S_LEN - 1) {
            memB[nb * 4096 + gh * 8 + bb] = mn;
            // stage x(t+1) (readers of xT2(t) finished before sync1)
            xdst[0] = xr.x; xdst[2] = xr.y; xdst[4] = xr.z; xdst[6] = xr.w;
            __syncthreads();

            if (tid == 0) {
                asm volatile("fence.proxy.async;" ::: "memory");
#pragma unroll
                for (int q = 0; q < 8; q++) {
                    const unsigned mb = mbar_base + (unsigned)((nb * 8 + q) * 8);
                    if (q == r) {
                        asm volatile("mbarrier.arrive.shared.b64 _, [%0];"
                                     :: "r"(mb) : "memory");
                    } else {
                        asm volatile("mbarrier.arrive.expect_tx.shared.b64 _, [%0], %1;"
                                     :: "r"(mb), "r"(2048) : "memory");
                    }
                }
                const unsigned doff = MEMB_BYTE + (unsigned)(nb * 16384 + r * 2048);
                const unsigned srcaddr = sbase + doff;
                const unsigned moff = MBAR_OFFB + (unsigned)((nb * 8 + r) * 8);
#pragma unroll
                for (int i = 1; i < 8; i++) {
                    const int q = (r + i) & 7;
                    unsigned pq;
                    asm("mapa.shared::cluster.u32 %0, %1, %2;" : "=r"(pq) : "r"(sbase), "r"(q));
                    asm volatile(
                        "cp.async.bulk.shared::cluster.shared::cta.mbarrier::complete_tx::bytes"
                        " [%0], [%1], %2, [%3];"
                        :: "r"(pq + doff), "r"(srcaddr), "r"(2048), "r"(pq + moff)
                        : "memory");
                }
            }
        } else {
            asm volatile("st.global.cg.f32 [%0], %1;"
                         :: "l"(g_buf + (size_t)cl * 4096 + gh * 8 + bb), "f"(mn) : "memory");
        }
    }

    // spike-count reduction
    __syncthreads();
    part[tid] = cnt;
    __syncthreads();
    if (tid < 256) part[tid] += part[tid + 256];
    __syncthreads();
    if (tid < 128) part[tid] += part[tid + 128];
    __syncthreads();
    if (tid < 64) part[tid] += part[tid + 64];
    __syncthreads();
    if (tid < 32) {
        float v = part[tid] + part[tid + 32];
#pragma unroll
        for (int o = 16; o > 0; o >>= 1) v += __shfl_down_sync(0xffffffffu, v, o);
        if (tid == 0) atomicAdd(&g_cnt, (int)(v + 0.5f));
    }
    CLUSTER_BARRIER();   // no CTA exits while peers' copies may still target its smem
}

// ---------------- readout GEMM + sparsity ----------------
__global__ void readout_kernel(const float* __restrict__ Wro, const float* __restrict__ bro,
                               float* __restrict__ out, int out_size)
{
    __shared__ float mrow[512];
    const int row = blockIdx.x;
    const int tid = threadIdx.x;   // 128
    const float* src = g_buf + (size_t)(row >> 3) * 4096 + (row & 7);
    for (int i = tid; i < 512; i += 128) mrow[i] = src[i * 8];
    __syncthreads();
    float acc = bro[tid];
#pragma unroll 8
    for (int k = 0; k < 512; k++)
        acc = fmaf(mrow[k], Wro[(size_t)k * 128 + tid], acc);
    out[(size_t)row * 128 + tid] = acc;
    if (row == 0 && tid == 0 && out_size > B_SZ * C_OUT) {
        out[B_SZ * C_OUT] = 1.0f - (float)g_cnt / (float)((size_t)S_LEN * B_SZ * H_SZ);
    }
}

// ---------------- launch ----------------
extern "C" void kernel_launch(void* const* d_in, const int* in_sizes, int n_in,
                              void* d_out, int out_size)
{
    const float* x    = (const float*)d_in[0];
    const float* Win  = (const float*)d_in[1];
    const float* bin  = (const float*)d_in[2];
    const float* Wtau = (const float*)d_in[3];
    const float* btl  = (const float*)d_in[4];
    const float* bt   = (const float*)d_in[5];
    const float* Wro  = (const float*)d_in[6];
    const float* bro  = (const float*)d_in[7];

    init_kernel<<<1, 1>>>();

    cudaFuncSetAttribute(fused_kernel, cudaFuncAttributeMaxDynamicSharedMemorySize, REC_SMEM);
    fused_kernel<<<128, 512, REC_SMEM>>>(x, Win, bin, Wtau, btl, bt);

    readout_kernel<<<B_SZ, C_OUT>>>(Wro, bro, (float*)d_out, out_size);
}

// round 17
// speedup vs baseline: 4.3019x; 1.8143x over previous
#include <cuda_runtime.h>
#include <cstdint>
#include <cstdio>

#define S_LEN 1024
#define B_SZ  128
#define D_IN  256
#define H_SZ  512
#define C_OUT 128

typedef unsigned long long ull;

// ---------------- f32x2 packed-FMA helpers (bit-identical per lane) ----------------
__device__ __forceinline__ ull ffma2(ull a, ull b, ull c) {
    ull d;
    asm("fma.rn.f32x2 %0, %1, %2, %3;" : "=l"(d) : "l"(a), "l"(b), "l"(c));
    return d;
}
__device__ __forceinline__ ull dup2(float v) {
    ull d;
    asm("mov.b64 %0, {%1, %1};" : "=l"(d) : "f"(v));
    return d;
}
__device__ __forceinline__ float2 unpack2(ull p) {
    float2 r;
    asm("mov.b64 {%0, %1}, %2;" : "=f"(r.x), "=f"(r.y) : "l"(p));
    return r;
}

// ---------------- device scratch ----------------
__device__ float g_T[(size_t)S_LEN * B_SZ * H_SZ];   // x@W_tau_x + b_tau_lin + b_tau
__device__ float g_G[(size_t)S_LEN * B_SZ * H_SZ];   // x@W_in + b_in
__device__ float g_buf[16 * 512 * 8];                // final mem: [cluster][h][b]
__device__ int   g_cnt;

__global__ void dummy_kernel() {}                    // shifts ncu sample onto recurrent_kernel
__global__ void init_kernel() { g_cnt = 0; }

// ---------------- Phase 1: fused precompute GEMM (FFMA2 over n-pairs; bit-identical) ----------------
__global__ __launch_bounds__(256, 2) void phase1_kernel(
    const float* __restrict__ x, const float* __restrict__ Win,
    const float* __restrict__ bin, const float* __restrict__ Wtau,
    const float* __restrict__ btl, const float* __restrict__ bt)
{
    __shared__ float As[2][16][128];   // As[k][m]
    __shared__ float Bs[2][16][128];   // Bs[k][n]

    const int tid = threadIdx.x;
    const int m0 = blockIdx.y * 128;
    const int n0 = blockIdx.x * 128;
    const bool isG = (n0 < 512);
    const float* __restrict__ Bp = isG ? (Win + n0) : (Wtau + (n0 - 512));

    const int q0 = tid, q1 = tid + 256;
    const int ar0 = q0 >> 2, ak0 = (q0 & 3) * 4;
    const int ar1 = q1 >> 2, ak1 = (q1 & 3) * 4;
    const int m_0 = m0 + ar0, m_1 = m0 + ar1;
    const float* ap0 = x + ((size_t)(m_0 & 127) * 1024 + (m_0 >> 7)) * 256 + ak0;
    const float* ap1 = x + ((size_t)(m_1 & 127) * 1024 + (m_1 >> 7)) * 256 + ak1;
    const int bk0 = q0 >> 5, bn0 = (q0 & 31) * 4;
    const int bk1 = q1 >> 5, bn1 = (q1 & 31) * 4;

    const int tx = tid & 15, ty = tid >> 4;
    const int c0 = tx * 4, c1 = tx * 4 + 64;
    const int r0 = ty * 4, r1 = ty * 4 + 64;

    ull acc2[8][4];
#pragma unroll
    for (int i = 0; i < 8; i++)
#pragma unroll
        for (int j = 0; j < 4; j++) acc2[i][j] = 0ull;

    float4 pa0 = *(const float4*)(ap0);
    float4 pa1 = *(const float4*)(ap1);
    float4 pb0 = *(const float4*)(Bp + (size_t)bk0 * 512 + bn0);
    float4 pb1 = *(const float4*)(Bp + (size_t)bk1 * 512 + bn1);

    As[0][ak0 + 0][ar0] = pa0.x; As[0][ak0 + 1][ar0] = pa0.y;
    As[0][ak0 + 2][ar0] = pa0.z; As[0][ak0 + 3][ar0] = pa0.w;
    As[0][ak1 + 0][ar1] = pa1.x; As[0][ak1 + 1][ar1] = pa1.y;
    As[0][ak1 + 2][ar1] = pa1.z; As[0][ak1 + 3][ar1] = pa1.w;
    *(float4*)&Bs[0][bk0][bn0] = pb0;
    *(float4*)&Bs[0][bk1][bn1] = pb1;
    __syncthreads();

    int p = 0;
    for (int kt = 0; kt < 16; kt++) {
        if (kt < 15) {
            const int kc = (kt + 1) * 16;
            pa0 = *(const float4*)(ap0 + kc);
            pa1 = *(const float4*)(ap1 + kc);
            pb0 = *(const float4*)(Bp + (size_t)(kc + bk0) * 512 + bn0);
            pb1 = *(const float4*)(Bp + (size_t)(kc + bk1) * 512 + bn1);
        }
#pragma unroll
        for (int k = 0; k < 16; k++) {
            float4 a0 = *(const float4*)&As[p][k][r0];
            float4 a1 = *(const float4*)&As[p][k][r1];
            const ull* bu0 = (const ull*)&Bs[p][k][c0];
            const ull* bu1 = (const ull*)&Bs[p][k][c1];
            ull bv[4] = {bu0[0], bu0[1], bu1[0], bu1[1]};
            float av[8] = {a0.x, a0.y, a0.z, a0.w, a1.x, a1.y, a1.z, a1.w};
#pragma unroll
            for (int i = 0; i < 8; i++) {
                const ull ad = dup2(av[i]);
#pragma unroll
                for (int j = 0; j < 4; j++)
                    acc2[i][j] = ffma2(ad, bv[j], acc2[i][j]);
            }
        }
        if (kt < 15) {
            const int np = p ^ 1;
            As[np][ak0 + 0][ar0] = pa0.x; As[np][ak0 + 1][ar0] = pa0.y;
            As[np][ak0 + 2][ar0] = pa0.z; As[np][ak0 + 3][ar0] = pa0.w;
            As[np][ak1 + 0][ar1] = pa1.x; As[np][ak1 + 1][ar1] = pa1.y;
            As[np][ak1 + 2][ar1] = pa1.z; As[np][ak1 + 3][ar1] = pa1.w;
            *(float4*)&Bs[np][bk0][bn0] = pb0;
            *(float4*)&Bs[np][bk1][bn1] = pb1;
        }
        __syncthreads();
        p ^= 1;
    }

    float* dst = isG ? g_G : g_T;
    const int coloff = isG ? n0 : (n0 - 512);
    float bias[8];
#pragma unroll
    for (int j = 0; j < 8; j++) {
        const int ncol = (j < 4) ? (c0 + j) : (c1 + j - 4);
        const int gb = coloff + ncol;
        bias[j] = isG ? bin[gb] : (btl[gb] + bt[gb]);
    }
#pragma unroll
    for (int i = 0; i < 8; i++) {
        const int mrow = m0 + ((i < 4) ? (r0 + i) : (r1 + i - 4));
        float2 u0 = unpack2(acc2[i][0]);
        float2 u1 = unpack2(acc2[i][1]);
        float2 u2 = unpack2(acc2[i][2]);
        float2 u3 = unpack2(acc2[i][3]);
        float4 o0 = make_float4(u0.x + bias[0], u0.y + bias[1],
                                u1.x + bias[2], u1.y + bias[3]);
        float4 o1 = make_float4(u2.x + bias[4], u2.y + bias[5],
                                u3.x + bias[6], u3.y + bias[7]);
        *(float4*)(dst + (size_t)mrow * 512 + coloff + c0) = o0;
        *(float4*)(dst + (size_t)mrow * 512 + coloff + c1) = o1;
    }
}

// ---------------- Phase 2: persistent recurrent kernel (R12 + distributed exchange issue) ----------------
__device__ __forceinline__ unsigned smem_u32_addr(const void* p) {
    unsigned a;
    asm("{ .reg .u64 t; cvta.to.shared.u64 t, %1; cvt.u32.u64 %0, t; }"
        : "=r"(a) : "l"(p));
    return a;
}

#define CLUSTER_BARRIER() \
    asm volatile("barrier.cluster.arrive.aligned;\n\tbarrier.cluster.wait.aligned;" ::: "memory")

// smem layout offsets (bytes) — Wm removed (weights live in registers)
#define MEMB_OFF   0                           // [2][512][8] floats
#define MEMB_BYTES (2 * 512 * 8 * 4)           // 32768
#define PART_OFF   (MEMB_OFF + MEMB_BYTES)     // [16][512] floats
#define PART_BYTES (16 * 512 * 4)              // 32768
#define MBAR_OFF   (PART_OFF + PART_BYTES)     // [2][8] x u64  (buffer, source rank)
#define REC_SMEM   (MBAR_OFF + 128)

__global__ void __cluster_dims__(8, 1, 1) __launch_bounds__(512, 1)
recurrent_kernel(const float* __restrict__ Wtau)
{
    extern __shared__ float sm[];
    float* memB = sm;                          // [2][512][8]  32 KB (h-major, batch contiguous)
    float* part = memB + 2 * 512 * 8;          // [16][512]    32 KB

    const int tid  = threadIdx.x;
    const int lane = tid & 31;
    const int w    = tid >> 5;                 // 0..15
    const int r    = blockIdx.x & 7;           // cluster rank -> column slice
    const int cl   = blockIdx.x >> 3;          // cluster index -> 8 batch rows
    const int b0   = cl * 8;

    const int k0 = w * 32;                     // warp K-split (32 k's per warp)

    // Weights in registers: this thread needs Wm[k0+kk][2*lane], Wm[k0+kk][2*lane+1]
    float wreg[64];
    {
        const float* wsrc = Wtau + (size_t)(256 + k0) * 512 + r * 64 + 2 * lane;
#pragma unroll
        for (int kk = 0; kk < 32; kk++) {
            const float2 wv = *(const float2*)(wsrc + (size_t)kk * 512);
            wreg[2 * kk]     = wv.x;
            wreg[2 * kk + 1] = wv.y;
        }
    }

    // Zero both mem buffers (t=0 input)
    for (int idx = tid; idx < 2 * 512 * 8; idx += 512) memB[idx] = 0.f;

    const unsigned sbase = smem_u32_addr(sm);
    const unsigned mbar_base = sbase + MBAR_OFF;
    if (tid < 16) {
        asm volatile("mbarrier.init.shared.b64 [%0], %1;"
                     :: "r"(mbar_base + tid * 8), "r"(1) : "memory");
    }
    CLUSTER_BARRIER();   // mbar init + memB zero visible cluster-wide

    // elementwise role: one cell (bb, ce) per thread
    const int ce = tid & 63;
    const int bb = tid >> 6;                   // batch 0..7
    const int gh = r * 64 + ce;                // global hidden col
    const int src = w >> 1;                    // the ONLY source rank this warp's k-range needs
    const unsigned my_mbar_b0 = mbar_base + (unsigned)(src * 8);   // buffer1 = +64 bytes

    float cnt = 0.f;

    for (int t = 0; t < S_LEN; t++) {
        const int cb = t & 1, nb = cb ^ 1;

        // prefetch T/G (consumed after GEMM)
        const size_t row = ((size_t)t * B_SZ + b0 + bb) * H_SZ + gh;
        const float Tv = g_T[row], Gv = g_G[row];

        // ---- per-warp wait: only my source slice of buffer cb must have landed ----
        if (t > 0) {
            const unsigned ph = (unsigned)(((t - 1) >> 1) & 1);
            const unsigned mb = my_mbar_b0 + (unsigned)(cb * 64);
            asm volatile(
                "{\n\t"
                ".reg .pred P;\n\t"
                "W_%=:\n\t"
                "mbarrier.try_wait.parity.acquire.cta.shared::cta.b64 P, [%0], %1, 0x989680;\n\t"
                "@P bra D_%=;\n\t"
                "bra W_%=;\n\t"
                "D_%=:\n\t"
                "}"
                :: "r"(mb), "r"(ph) : "memory");
        }

        // ---- GEMM: out[b][c] = sum_k memB[cb][k][b] * W[k][c]  (FFMA2, weights in regs) ----
        ull pa[4], pb[4];
#pragma unroll
        for (int j = 0; j < 4; j++) { pa[j] = 0ull; pb[j] = 0ull; }

        const float* mp = memB + cb * 4096 + k0 * 8;
#pragma unroll
        for (int kk = 0; kk < 32; kk++) {
            const ulonglong2 m01 = *(const ulonglong2*)(mp + kk * 8);
            const ulonglong2 m23 = *(const ulonglong2*)(mp + kk * 8 + 4);
            const ull w0d = dup2(wreg[2 * kk]);
            const ull w1d = dup2(wreg[2 * kk + 1]);
            pa[0] = ffma2(m01.x, w0d, pa[0]);
            pa[1] = ffma2(m01.y, w0d, pa[1]);
            pa[2] = ffma2(m23.x, w0d, pa[2]);
            pa[3] = ffma2(m23.y, w0d, pa[3]);
            pb[0] = ffma2(m01.x, w1d, pb[0]);
            pb[1] = ffma2(m01.y, w1d, pb[1]);
            pb[2] = ffma2(m23.x, w1d, pb[2]);
            pb[3] = ffma2(m23.y, w1d, pb[3]);
        }
#pragma unroll
        for (int j = 0; j < 4; j++) {
            const float2 fa = unpack2(pa[j]);
            const float2 fb = unpack2(pb[j]);
            *(float2*)&part[w * 512 + (2 * j)     * 64 + 2 * lane] = make_float2(fa.x, fb.x);
            *(float2*)&part[w * 512 + (2 * j + 1) * 64 + 2 * lane] = make_float2(fa.y, fb.y);
        }
        __syncthreads();

        // ---- reduce 16 warp partials + elementwise update for cell (bb, ce) ----
        float s = 0.f;
#pragma unroll
        for (int ww = 0; ww < 16; ww++)
            s += part[ww * 512 + bb * 64 + ce];
        const float l = Tv + s;
        float beta = 1.f / (1.f + expf(-l));
        beta = fminf(fmaxf(beta, 0.01f), 0.99f);
        const float mo = memB[cb * 4096 + gh * 8 + bb];
        float mn = fmaf(beta, mo, Gv);
        const float sp = ((mn - 1.0f) > 0.0f) ? 1.f : 0.f;
        mn -= sp;
        cnt += sp;

        if (t < S_LEN - 1) {
            // write my slice into my own next buffer
            memB[nb * 4096 + gh * 8 + bb] = mn;
            __syncthreads();   // slice fully written; all GEMM reads of memB[cb] done too

            // distributed exchange issuance: tid 0..7 arm one barrier each,
            // tid 0..6 send one 2KB slice copy each (mapa inline, no pbase array)
            if (tid < 8) {
                asm volatile("fence.proxy.async;" ::: "memory");
                const unsigned mb = mbar_base + (unsigned)((nb * 8 + tid) * 8);
                if (tid == r) {
                    asm volatile("mbarrier.arrive.shared.b64 _, [%0];"
                                 :: "r"(mb) : "memory");
                } else {
                    asm volatile("mbarrier.arrive.expect_tx.shared.b64 _, [%0], %1;"
                                 :: "r"(mb), "r"(2048) : "memory");
                }
                if (tid < 7) {
                    const int q = (r + 1 + tid) & 7;
                    const unsigned doff = MEMB_OFF + (unsigned)(nb * 16384 + r * 2048);
                    const unsigned moff = MBAR_OFF + (unsigned)((nb * 8 + r) * 8);
                    unsigned pq;
                    asm("mapa.shared::cluster.u32 %0, %1, %2;" : "=r"(pq) : "r"(sbase), "r"(q));
                    asm volatile(
                        "cp.async.bulk.shared::cluster.shared::cta.mbarrier::complete_tx::bytes"
                        " [%0], [%1], %2, [%3];"
                        :: "r"(pq + doff), "r"(sbase + doff), "r"(2048), "r"(pq + moff)
                        : "memory");
                }
            }
            // NO cluster-wide wait here: each warp waits on its own slice next step.
        } else {
            // final step: publish my value straight to gmem for the readout
            asm volatile("st.global.cg.f32 [%0], %1;"
                         :: "l"(g_buf + (size_t)cl * 4096 + gh * 8 + bb), "f"(mn) : "memory");
        }
    }

    // spike-count reduction (512 threads)
    __syncthreads();
    part[tid] = cnt;
    __syncthreads();
    if (tid < 256) part[tid] += part[tid + 256];
    __syncthreads();
    if (tid < 128) part[tid] += part[tid + 128];
    __syncthreads();
    if (tid < 64) part[tid] += part[tid + 64];
    __syncthreads();
    if (tid < 32) {
        float v = part[tid] + part[tid + 32];
#pragma unroll
        for (int o = 16; o > 0; o >>= 1) v += __shfl_down_sync(0xffffffffu, v, o);
        if (tid == 0) atomicAdd(&g_cnt, (int)(v + 0.5f));
    }
    CLUSTER_BARRIER();   // no CTA exits while peers' copies may still target its smem
}

// ---------------- Phase 3: readout GEMM + sparsity ----------------
__global__ void readout_kernel(const float* __restrict__ Wro, const float* __restrict__ bro,
                               float* __restrict__ out, int out_size)
{
    __shared__ float mrow[512];
    const int row = blockIdx.x;
    const int tid = threadIdx.x;   // 128
    const float* src = g_buf + (size_t)(row >> 3) * 4096 + (row & 7);
    for (int i = tid; i < 512; i += 128) mrow[i] = src[i * 8];
    __syncthreads();
    float acc = bro[tid];
#pragma unroll 8
    for (int k = 0; k < 512; k++)
        acc = fmaf(mrow[k], Wro[(size_t)k * 128 + tid], acc);
    out[(size_t)row * 128 + tid] = acc;
    if (row == 0 && tid == 0 && out_size > B_SZ * C_OUT) {
        out[B_SZ * C_OUT] = 1.0f - (float)g_cnt / (float)((size_t)S_LEN * B_SZ * H_SZ);
    }
}

// ---------------- launch ----------------
extern "C" void kernel_launch(void* const* d_in, const int* in_sizes, int n_in,
                              void* d_out, int out_size)
{
    const float* x    = (const float*)d_in[0];
    const float* Win  = (const float*)d_in[1];
    const float* bin  = (const float*)d_in[2];
    const float* Wtau = (const float*)d_in[3];
    const float* btl  = (const float*)d_in[4];
    const float* bt   = (const float*)d_in[5];
    const float* Wro  = (const float*)d_in[6];
    const float* bro  = (const float*)d_in[7];

    dummy_kernel<<<1, 1>>>();   // shifts recurrent_kernel to absolute launch #4 for ncu
    init_kernel<<<1, 1>>>();

    dim3 g1(8, 1024);   // n-tiles x m-tiles
    phase1_kernel<<<g1, 256>>>(x, Win, bin, Wtau, btl, bt);

    cudaFuncSetAttribute(recurrent_kernel, cudaFuncAttributeMaxDynamicSharedMemorySize, REC_SMEM);
    recurrent_kernel<<<128, 512, REC_SMEM>>>(Wtau);

    readout_kernel<<<B_SZ, C_OUT>>>(Wro, bro, (float*)d_out, out_size);
}